// round 14
// baseline (speedup 1.0000x reference)
#include <cuda_runtime.h>
#include <cuda_fp16.h>
#include <cstdint>

#define N_NODES 50000
#define N_EDGES 800000
#define DIM     128
#define DIM2    64                    // DIM/2 (u32 units per row)
#define LAYERS  5

#define SCAN_BLOCKS 196               // ceil(50000/256)
#define FEAT_BLOCKS 12500             // 50000*64/256
#define WSPL_BLOCKS 160               // 5*64*128/256
#define ZERO_BLOCKS 196

#define FLAG_AGG    (1u << 30)
#define FLAG_PRE    (2u << 30)
#define VAL_MASK    0x3FFFFFFFu

// fused-kernel smem (u32 units)
#define AS_STRIDE   68                        // 64 + 4 pad
#define A_SMEM_U32  (128 * AS_STRIDE)         // 8704
#define W_SMEM_U32  (16 * 136)                // 2176 per array
#define FUSED_SMEM  ((A_SMEM_U32 + 2 * W_SMEM_U32) * 4)   // 52224 B

// ---------------- scratch (no allocation allowed) ----------------
__device__ unsigned g_feat16[N_NODES * DIM2];    // feat as half2
__device__ unsigned g_h16[2][N_NODES * DIM2];    // ping-pong hidden, half2
__device__ unsigned g_Whl[2][LAYERS * DIM2 * DIM]; // W hi/lo, [l][k2][n]
__device__ int      g_deg_out[N_NODES];
__device__ int      g_deg_in[N_NODES];
__device__ float    g_norm_src[N_NODES];
__device__ int      g_row_ptr[N_NODES + 1];
__device__ int      g_cursor[N_NODES];
__device__ int2     g_csr[N_EDGES];
__device__ unsigned g_scan_state[SCAN_BLOCKS];

// fp16 mma: D(16x8,f32) += A(16x16,f16) * B(16x8,f16)
__device__ __forceinline__ void mma_f16(float c[4], const uint32_t a[4],
                                        uint32_t b0, uint32_t b1) {
    asm volatile(
        "mma.sync.aligned.m16n8k16.row.col.f32.f16.f16.f32 "
        "{%0,%1,%2,%3}, {%4,%5,%6,%7}, {%8,%9}, {%0,%1,%2,%3};"
        : "+f"(c[0]), "+f"(c[1]), "+f"(c[2]), "+f"(c[3])
        : "r"(a[0]), "r"(a[1]), "r"(a[2]), "r"(a[3]), "r"(b0), "r"(b1));
}

// ---------------- fused init: feat->fp16, W split, zero deg/state ----------
__global__ __launch_bounds__(256)
void init_kernel(const float* __restrict__ feat, const float* __restrict__ W) {
    int bid = blockIdx.x;
    if (bid < FEAT_BLOCKS) {
        int i = bid * 256 + threadIdx.x;
        float2 f = ((const float2*)feat)[i];
        __half2 h = __floats2half2_rn(f.x, f.y);
        g_feat16[i] = *(unsigned*)&h;
    } else if (bid < FEAT_BLOCKS + WSPL_BLOCKS) {
        int i = (bid - FEAT_BLOCKS) * 256 + threadIdx.x;
        int n  = i & 127;
        int k2 = (i >> 7) & 63;
        int l  = i >> 13;
        float w0 = W[l * DIM * DIM + (2 * k2)     * DIM + n];
        float w1 = W[l * DIM * DIM + (2 * k2 + 1) * DIM + n];
        __half h0 = __float2half_rn(w0);
        __half h1 = __float2half_rn(w1);
        float r0 = w0 - __half2float(h0);
        float r1 = w1 - __half2float(h1);
        __half2 hi = __halves2half2(h0, h1);
        __half2 lo = __floats2half2_rn(r0, r1);
        g_Whl[0][i] = *(unsigned*)&hi;
        g_Whl[1][i] = *(unsigned*)&lo;
    } else {
        int i = (bid - FEAT_BLOCKS - WSPL_BLOCKS) * 256 + threadIdx.x;
        if (i < N_NODES) { g_deg_out[i] = 0; g_deg_in[i] = 0; }
        if (i < SCAN_BLOCKS) g_scan_state[i] = 0u;
    }
}

// ---------------- degree count ----------------
__global__ void count_deg_kernel(const int* __restrict__ src,
                                 const int* __restrict__ dst) {
    int e = blockIdx.x * blockDim.x + threadIdx.x;
    if (e < N_EDGES) {
        atomicAdd(&g_deg_out[src[e]], 1);
        atomicAdd(&g_deg_in[dst[e]], 1);
    }
}

// ---------------- single-kernel decoupled-lookback scan ----------------
__global__ __launch_bounds__(256)
void scan_fused_kernel() {
    __shared__ int wsum[8];
    __shared__ int s_excl;
    int tid  = threadIdx.x;
    int lane = tid & 31;
    int wid  = tid >> 5;
    int bid  = blockIdx.x;
    int i    = bid * 256 + tid;

    int deg = (i < N_NODES) ? g_deg_in[i] : 0;

    int v = deg;
    #pragma unroll
    for (int o = 1; o < 32; o <<= 1) {
        int n = __shfl_up_sync(0xFFFFFFFFu, v, o);
        if (lane >= o) v += n;
    }
    if (lane == 31) wsum[wid] = v;
    __syncthreads();
    if (wid == 0) {
        int s = (lane < 8) ? wsum[lane] : 0;
        #pragma unroll
        for (int o = 1; o < 8; o <<= 1) {
            int n = __shfl_up_sync(0xFFFFFFFFu, s, o);
            if (lane >= o) s += n;
        }
        if (lane < 8) wsum[lane] = s;
    }
    __syncthreads();
    int incl = v + (wid > 0 ? wsum[wid - 1] : 0);
    int btot = wsum[7];

    if (tid == 0) {
        unsigned pub = (bid == 0) ? (FLAG_PRE | (unsigned)btot)
                                  : (FLAG_AGG | (unsigned)btot);
        atomicExch(&g_scan_state[bid], pub);
        if (bid == 0) s_excl = 0;
    }

    if (bid > 0 && wid == 0) {
        int excl = 0;
        int look = bid - 1;
        while (true) {
            int idx = look - lane;
            unsigned s;
            do {
                s = (idx >= 0) ? atomicAdd(&g_scan_state[idx], 0u)
                               : FLAG_PRE;
            } while (s == 0u);
            unsigned pmask = __ballot_sync(0xFFFFFFFFu, (s >> 30) == 2u);
            int val;
            if (pmask) {
                int plane = __ffs(pmask) - 1;
                val = (lane <= plane) ? (int)(s & VAL_MASK) : 0;
            } else {
                val = (int)(s & VAL_MASK);
            }
            #pragma unroll
            for (int o = 16; o > 0; o >>= 1)
                val += __shfl_down_sync(0xFFFFFFFFu, val, o);
            excl += __shfl_sync(0xFFFFFFFFu, val, 0);
            if (pmask) break;
            look -= 32;
        }
        if (lane == 0) {
            s_excl = excl;
            atomicExch(&g_scan_state[bid], FLAG_PRE | (unsigned)(excl + btot));
        }
    }
    __syncthreads();

    int excl_t = s_excl + incl - deg;
    if (i < N_NODES) {
        g_row_ptr[i] = excl_t;
        g_cursor[i]  = excl_t;
        if (i == N_NODES - 1) g_row_ptr[N_NODES] = excl_t + deg;
        g_norm_src[i] = rsqrtf(fmaxf((float)g_deg_out[i], 1.0f));
    }
}

// ---------------- scatter edges into packed CSR --------------------------
__global__ void scatter_edges_kernel(const int* __restrict__ src,
                                     const int* __restrict__ dst) {
    int e = blockIdx.x * blockDim.x + threadIdx.x;
    if (e < N_EDGES) {
        int s = src[e];
        int d = dst[e];
        int pos = atomicAdd(&g_cursor[d], 1);
        float nd = rsqrtf(fmaxf((float)g_deg_in[d], 1.0f));
        g_csr[pos] = make_int2(s, __float_as_int(g_norm_src[s] * nd));
    }
}

// ---------------- fused layer: SpMM (gather -> smem A) + fp16 MMA GEMM ----
// CTA = 128 node rows. Phase 1: warp-per-node CSR gather (HFMA2 chains),
// result packed fp16 directly into the smem A tile (no gmem agg buffer).
// Phase 2: 2-pass W-compensated fp16 tensor GEMM out of smem.
__global__ __launch_bounds__(256, 3)
void fused_layer_kernel(const float* __restrict__ bias_p,
                        float* __restrict__ ext_out,
                        int layer, int in_sel, int out_sel) {
    extern __shared__ uint32_t smem[];
    uint32_t* Aall = smem;                         // [128][AS_STRIDE]
    uint32_t* Whi  = smem + A_SMEM_U32;            // [16][136]
    uint32_t* Wlo  = Whi + W_SMEM_U32;             // [16][136]

    const unsigned* __restrict__ h = (in_sel < 0) ? g_feat16 : g_h16[in_sel];
    const int2* __restrict__ csr = g_csr;

    const int tid  = threadIdx.x;
    const int lane = tid & 31;
    const int wrp  = tid >> 5;
    const int rowBase = blockIdx.x * 128;

    // ---------------- phase 1: SpMM into smem A tile ----------------
    for (int n = 0; n < 16; n++) {
        int localRow = n * 8 + wrp;
        int node = rowBase + localRow;

        float4 acc = make_float4(0.f, 0.f, 0.f, 0.f);
        if (node < N_NODES) {
            int beg = g_row_ptr[node];
            int end = g_row_ptr[node + 1];
            int i = beg;
            for (; i + 7 < end; i += 8) {
                int2 e0 = csr[i];
                int2 e1 = csr[i + 1];
                int2 e2 = csr[i + 2];
                int2 e3 = csr[i + 3];
                int2 e4 = csr[i + 4];
                int2 e5 = csr[i + 5];
                int2 e6 = csr[i + 6];
                int2 e7 = csr[i + 7];
                uint2 v0 = ((const uint2*)(h + (size_t)e0.x * DIM2))[lane];
                uint2 v1 = ((const uint2*)(h + (size_t)e1.x * DIM2))[lane];
                uint2 v2 = ((const uint2*)(h + (size_t)e2.x * DIM2))[lane];
                uint2 v3 = ((const uint2*)(h + (size_t)e3.x * DIM2))[lane];
                uint2 v4 = ((const uint2*)(h + (size_t)e4.x * DIM2))[lane];
                uint2 v5 = ((const uint2*)(h + (size_t)e5.x * DIM2))[lane];
                uint2 v6 = ((const uint2*)(h + (size_t)e6.x * DIM2))[lane];
                uint2 v7 = ((const uint2*)(h + (size_t)e7.x * DIM2))[lane];

                __half2 w0 = __float2half2_rn(__int_as_float(e0.y));
                __half2 w1 = __float2half2_rn(__int_as_float(e1.y));
                __half2 w2 = __float2half2_rn(__int_as_float(e2.y));
                __half2 w3 = __float2half2_rn(__int_as_float(e3.y));
                __half2 w4 = __float2half2_rn(__int_as_float(e4.y));
                __half2 w5 = __float2half2_rn(__int_as_float(e5.y));
                __half2 w6 = __float2half2_rn(__int_as_float(e6.y));
                __half2 w7 = __float2half2_rn(__int_as_float(e7.y));

                __half2 p0 = __hmul2(*(__half2*)&v0.x, w0);
                __half2 p1 = __hmul2(*(__half2*)&v0.y, w0);
                p0 = __hfma2(*(__half2*)&v1.x, w1, p0);
                p1 = __hfma2(*(__half2*)&v1.y, w1, p1);
                p0 = __hfma2(*(__half2*)&v2.x, w2, p0);
                p1 = __hfma2(*(__half2*)&v2.y, w2, p1);
                p0 = __hfma2(*(__half2*)&v3.x, w3, p0);
                p1 = __hfma2(*(__half2*)&v3.y, w3, p1);
                __half2 q0 = __hmul2(*(__half2*)&v4.x, w4);
                __half2 q1 = __hmul2(*(__half2*)&v4.y, w4);
                q0 = __hfma2(*(__half2*)&v5.x, w5, q0);
                q1 = __hfma2(*(__half2*)&v5.y, w5, q1);
                q0 = __hfma2(*(__half2*)&v6.x, w6, q0);
                q1 = __hfma2(*(__half2*)&v6.y, w6, q1);
                q0 = __hfma2(*(__half2*)&v7.x, w7, q0);
                q1 = __hfma2(*(__half2*)&v7.y, w7, q1);

                float2 f0 = __half22float2(p0);
                float2 f1 = __half22float2(p1);
                float2 g0 = __half22float2(q0);
                float2 g1 = __half22float2(q1);
                acc.x += f0.x + g0.x; acc.y += f0.y + g0.y;
                acc.z += f1.x + g1.x; acc.w += f1.y + g1.y;
            }
            for (; i + 3 < end; i += 4) {
                int2 e0 = csr[i];
                int2 e1 = csr[i + 1];
                int2 e2 = csr[i + 2];
                int2 e3 = csr[i + 3];
                uint2 v0 = ((const uint2*)(h + (size_t)e0.x * DIM2))[lane];
                uint2 v1 = ((const uint2*)(h + (size_t)e1.x * DIM2))[lane];
                uint2 v2 = ((const uint2*)(h + (size_t)e2.x * DIM2))[lane];
                uint2 v3 = ((const uint2*)(h + (size_t)e3.x * DIM2))[lane];
                __half2 w0 = __float2half2_rn(__int_as_float(e0.y));
                __half2 w1 = __float2half2_rn(__int_as_float(e1.y));
                __half2 w2 = __float2half2_rn(__int_as_float(e2.y));
                __half2 w3 = __float2half2_rn(__int_as_float(e3.y));
                __half2 p0 = __hmul2(*(__half2*)&v0.x, w0);
                __half2 p1 = __hmul2(*(__half2*)&v0.y, w0);
                p0 = __hfma2(*(__half2*)&v1.x, w1, p0);
                p1 = __hfma2(*(__half2*)&v1.y, w1, p1);
                p0 = __hfma2(*(__half2*)&v2.x, w2, p0);
                p1 = __hfma2(*(__half2*)&v2.y, w2, p1);
                p0 = __hfma2(*(__half2*)&v3.x, w3, p0);
                p1 = __hfma2(*(__half2*)&v3.y, w3, p1);
                float2 f0 = __half22float2(p0);
                float2 f1 = __half22float2(p1);
                acc.x += f0.x; acc.y += f0.y; acc.z += f1.x; acc.w += f1.y;
            }
            for (; i < end; i++) {
                int2 e0 = csr[i];
                float w = __int_as_float(e0.y);
                uint2 v0 = ((const uint2*)(h + (size_t)e0.x * DIM2))[lane];
                float2 a = __half22float2(*(__half2*)&v0.x);
                float2 b = __half22float2(*(__half2*)&v0.y);
                acc.x += a.x * w; acc.y += a.y * w;
                acc.z += b.x * w; acc.w += b.y * w;
            }
        }
        __half2 h01 = __floats2half2_rn(acc.x, acc.y);
        __half2 h23 = __floats2half2_rn(acc.z, acc.w);
        uint2 pk;
        pk.x = *(unsigned*)&h01;
        pk.y = *(unsigned*)&h23;
        *(uint2*)&Aall[localRow * AS_STRIDE + 2 * lane] = pk;
    }

    // ---------------- phase 2: GEMM from smem A ----------------
    const unsigned* __restrict__ Wh = g_Whl[0] + (size_t)layer * DIM2 * DIM;
    const unsigned* __restrict__ Wl = g_Whl[1] + (size_t)layer * DIM2 * DIM;

    const int wm = wrp & 3;       // 4 M quarters (32 rows)
    const int wn = wrp >> 2;      // 2 N halves (64 cols)
    const int gid = lane >> 2;
    const int tg  = lane & 3;

    float C[2][8][4];
    #pragma unroll
    for (int mt = 0; mt < 2; mt++)
        #pragma unroll
        for (int nt = 0; nt < 8; nt++)
            #pragma unroll
            for (int q = 0; q < 4; q++) C[mt][nt][q] = 0.0f;

    for (int kc2 = 0; kc2 < DIM2; kc2 += 16) {   // 4 chunks of 32 k
        __syncthreads();   // first iter: orders phase-1 A writes; later: W reuse
        #pragma unroll
        for (int it = 0; it < 2; it++) {
            int f  = tid + it * 256;
            int kk = f >> 5;
            int nn = (f & 31) * 4;
            *(uint4*)&Whi[kk * 136 + nn] =
                *(const uint4*)&Wh[(size_t)(kc2 + kk) * DIM + nn];
            *(uint4*)&Wlo[kk * 136 + nn] =
                *(const uint4*)&Wl[(size_t)(kc2 + kk) * DIM + nn];
        }
        __syncthreads();

        #pragma unroll
        for (int k8 = 0; k8 < 2; k8++) {
            uint32_t a[2][4];
            #pragma unroll
            for (int mt = 0; mt < 2; mt++) {
                int r0 = wm * 32 + mt * 16 + gid;
                int c0 = kc2 + k8 * 8 + tg;
                a[mt][0] = Aall[r0 * AS_STRIDE + c0];
                a[mt][1] = Aall[(r0 + 8) * AS_STRIDE + c0];
                a[mt][2] = Aall[r0 * AS_STRIDE + c0 + 4];
                a[mt][3] = Aall[(r0 + 8) * AS_STRIDE + c0 + 4];
            }
            #pragma unroll
            for (int nt = 0; nt < 8; nt++) {
                int n = wn * 64 + nt * 8 + gid;
                int k = k8 * 8 + tg;
                uint32_t bh0 = Whi[k * 136 + n];
                uint32_t bh1 = Whi[(k + 4) * 136 + n];
                uint32_t bl0 = Wlo[k * 136 + n];
                uint32_t bl1 = Wlo[(k + 4) * 136 + n];
                #pragma unroll
                for (int mt = 0; mt < 2; mt++) {
                    mma_f16(C[mt][nt], a[mt], bh0, bh1);   // A * Whi
                    mma_f16(C[mt][nt], a[mt], bl0, bl1);   // A * Wlo
                }
            }
        }
    }

    // epilogue: bias + relu; fp16 half2 hidden, fp32 final
    unsigned* __restrict__ out16 = (out_sel < 0) ? nullptr : g_h16[out_sel];
    #pragma unroll
    for (int nt = 0; nt < 8; nt++) {
        int col = wn * 64 + nt * 8 + 2 * tg;
        float b0 = bias_p[col];
        float b1 = bias_p[col + 1];
        #pragma unroll
        for (int mt = 0; mt < 2; mt++) {
            int row = rowBase + wm * 32 + mt * 16 + gid;
            float x0 = fmaxf(C[mt][nt][0] + b0, 0.f);
            float y0 = fmaxf(C[mt][nt][1] + b1, 0.f);
            float x1 = fmaxf(C[mt][nt][2] + b0, 0.f);
            float y1 = fmaxf(C[mt][nt][3] + b1, 0.f);
            if (out_sel < 0) {
                if (row < N_NODES)
                    *(float2*)&ext_out[(size_t)row * DIM + col] =
                        make_float2(x0, y0);
                if (row + 8 < N_NODES)
                    *(float2*)&ext_out[(size_t)(row + 8) * DIM + col] =
                        make_float2(x1, y1);
            } else {
                if (row < N_NODES) {
                    __half2 hv = __floats2half2_rn(x0, y0);
                    out16[(size_t)row * DIM2 + (col >> 1)] = *(unsigned*)&hv;
                }
                if (row + 8 < N_NODES) {
                    __half2 hv = __floats2half2_rn(x1, y1);
                    out16[(size_t)(row + 8) * DIM2 + (col >> 1)] = *(unsigned*)&hv;
                }
            }
        }
    }
}

// ---------------- launch ----------------
extern "C" void kernel_launch(void* const* d_in, const int* in_sizes, int n_in,
                              void* d_out, int out_size) {
    const float* feat = (const float*)d_in[0];   // [N, D]
    const int*   src  = (const int*)d_in[1];     // [E]
    const int*   dst  = (const int*)d_in[2];     // [E]
    const float* W    = (const float*)d_in[3];   // [L, D, D]
    const float* b    = (const float*)d_in[4];   // [L, D]
    float* out = (float*)d_out;                  // [N, D]

    (void)in_sizes; (void)n_in; (void)out_size;

    cudaFuncSetAttribute(fused_layer_kernel,
                         cudaFuncAttributeMaxDynamicSharedMemorySize,
                         FUSED_SMEM);

    init_kernel<<<FEAT_BLOCKS + WSPL_BLOCKS + ZERO_BLOCKS, 256>>>(feat, W);
    count_deg_kernel<<<(N_EDGES + 255) / 256, 256>>>(src, dst);
    scan_fused_kernel<<<SCAN_BLOCKS, 256>>>();
    scatter_edges_kernel<<<(N_EDGES + 255) / 256, 256>>>(src, dst);

    const int blocks = (N_NODES + 127) / 128;    // 391

    for (int l = 0; l < LAYERS; l++) {
        int in_sel  = (l == 0) ? -1 : ((l - 1) & 1);
        int out_sel = (l == LAYERS - 1) ? -1 : (l & 1);

        fused_layer_kernel<<<blocks, 256, FUSED_SMEM>>>(
            b + (size_t)l * DIM, out, l, in_sel, out_sel);
    }
}

// round 15
// speedup vs baseline: 1.1026x; 1.1026x over previous
#include <cuda_runtime.h>
#include <cuda_fp16.h>
#include <cstdint>

#define N_NODES 50000
#define N_EDGES 800000
#define DIM     128
#define DIM2    64                    // DIM/2 (u32 units per row)
#define LAYERS  5

#define SCAN_BLOCKS 196               // ceil(50000/256)
#define FEAT_BLOCKS 12500             // 50000*64/256
#define WSPL_BLOCKS 160               // 5*64*128/256
#define CNT_BLOCKS  3125              // 800000/256

#define FLAG_AGG    (1u << 30)
#define FLAG_PRE    (2u << 30)
#define VAL_MASK    0x3FFFFFFFu

// ---------------- scratch (no allocation allowed) ----------------
// g_deg_*, g_scan_state are zero at module load and restored to zero by
// cleanup_kernel at the end of every launch (launch-invariant state).
__device__ unsigned g_feat16[N_NODES * DIM2];    // feat as half2
__device__ unsigned g_h16[2][N_NODES * DIM2];    // ping-pong hidden, half2
__device__ unsigned g_agg16[N_NODES * DIM2];     // aggregation, half2
__device__ unsigned g_Whl[2][LAYERS * DIM2 * DIM]; // W hi/lo, [l][k2][n]
__device__ int      g_deg_out[N_NODES];
__device__ int      g_deg_in[N_NODES];
__device__ float    g_norm_src[N_NODES];
__device__ int      g_row_ptr[N_NODES + 1];
__device__ int      g_cursor[N_NODES];
__device__ int2     g_csr[N_EDGES];
__device__ unsigned g_scan_state[SCAN_BLOCKS];

// fp16 mma: D(16x8,f32) += A(16x16,f16) * B(16x8,f16)
__device__ __forceinline__ void mma_f16(float c[4], const uint32_t a[4],
                                        uint32_t b0, uint32_t b1) {
    asm volatile(
        "mma.sync.aligned.m16n8k16.row.col.f32.f16.f16.f32 "
        "{%0,%1,%2,%3}, {%4,%5,%6,%7}, {%8,%9}, {%0,%1,%2,%3};"
        : "+f"(c[0]), "+f"(c[1]), "+f"(c[2]), "+f"(c[3])
        : "r"(a[0]), "r"(a[1]), "r"(a[2]), "r"(a[3]), "r"(b0), "r"(b1));
}

// ---------------- fused init: feat->fp16, W split, degree count ------------
// Degree arrays are zero on entry (module-load init / cleanup_kernel).
__global__ __launch_bounds__(256)
void init_kernel(const float* __restrict__ feat, const float* __restrict__ W,
                 const int* __restrict__ src, const int* __restrict__ dst) {
    int bid = blockIdx.x;
    if (bid < FEAT_BLOCKS) {
        int i = bid * 256 + threadIdx.x;
        float2 f = ((const float2*)feat)[i];
        __half2 h = __floats2half2_rn(f.x, f.y);
        g_feat16[i] = *(unsigned*)&h;
    } else if (bid < FEAT_BLOCKS + WSPL_BLOCKS) {
        int i = (bid - FEAT_BLOCKS) * 256 + threadIdx.x;
        int n  = i & 127;
        int k2 = (i >> 7) & 63;
        int l  = i >> 13;
        float w0 = W[l * DIM * DIM + (2 * k2)     * DIM + n];
        float w1 = W[l * DIM * DIM + (2 * k2 + 1) * DIM + n];
        __half h0 = __float2half_rn(w0);
        __half h1 = __float2half_rn(w1);
        float r0 = w0 - __half2float(h0);
        float r1 = w1 - __half2float(h1);
        __half2 hi = __halves2half2(h0, h1);
        __half2 lo = __floats2half2_rn(r0, r1);
        g_Whl[0][i] = *(unsigned*)&hi;
        g_Whl[1][i] = *(unsigned*)&lo;
    } else {
        int e = (bid - FEAT_BLOCKS - WSPL_BLOCKS) * 256 + threadIdx.x;
        if (e < N_EDGES) {
            atomicAdd(&g_deg_out[src[e]], 1);
            atomicAdd(&g_deg_in[dst[e]], 1);
        }
    }
}

// ---------------- cleanup: restore zeroed state for next launch ------------
__global__ __launch_bounds__(256)
void cleanup_kernel() {
    int i = blockIdx.x * 256 + threadIdx.x;
    if (i < N_NODES) { g_deg_out[i] = 0; g_deg_in[i] = 0; }
    if (i < SCAN_BLOCKS) g_scan_state[i] = 0u;
}

// ---------------- single-kernel decoupled-lookback scan ----------------
__global__ __launch_bounds__(256)
void scan_fused_kernel() {
    __shared__ int wsum[8];
    __shared__ int s_excl;
    int tid  = threadIdx.x;
    int lane = tid & 31;
    int wid  = tid >> 5;
    int bid  = blockIdx.x;
    int i    = bid * 256 + tid;

    int deg = (i < N_NODES) ? g_deg_in[i] : 0;

    int v = deg;
    #pragma unroll
    for (int o = 1; o < 32; o <<= 1) {
        int n = __shfl_up_sync(0xFFFFFFFFu, v, o);
        if (lane >= o) v += n;
    }
    if (lane == 31) wsum[wid] = v;
    __syncthreads();
    if (wid == 0) {
        int s = (lane < 8) ? wsum[lane] : 0;
        #pragma unroll
        for (int o = 1; o < 8; o <<= 1) {
            int n = __shfl_up_sync(0xFFFFFFFFu, s, o);
            if (lane >= o) s += n;
        }
        if (lane < 8) wsum[lane] = s;
    }
    __syncthreads();
    int incl = v + (wid > 0 ? wsum[wid - 1] : 0);
    int btot = wsum[7];

    if (tid == 0) {
        unsigned pub = (bid == 0) ? (FLAG_PRE | (unsigned)btot)
                                  : (FLAG_AGG | (unsigned)btot);
        atomicExch(&g_scan_state[bid], pub);
        if (bid == 0) s_excl = 0;
    }

    if (bid > 0 && wid == 0) {
        int excl = 0;
        int look = bid - 1;
        while (true) {
            int idx = look - lane;
            unsigned s;
            do {
                s = (idx >= 0) ? atomicAdd(&g_scan_state[idx], 0u)
                               : FLAG_PRE;
            } while (s == 0u);
            unsigned pmask = __ballot_sync(0xFFFFFFFFu, (s >> 30) == 2u);
            int val;
            if (pmask) {
                int plane = __ffs(pmask) - 1;
                val = (lane <= plane) ? (int)(s & VAL_MASK) : 0;
            } else {
                val = (int)(s & VAL_MASK);
            }
            #pragma unroll
            for (int o = 16; o > 0; o >>= 1)
                val += __shfl_down_sync(0xFFFFFFFFu, val, o);
            excl += __shfl_sync(0xFFFFFFFFu, val, 0);
            if (pmask) break;
            look -= 32;
        }
        if (lane == 0) {
            s_excl = excl;
            atomicExch(&g_scan_state[bid], FLAG_PRE | (unsigned)(excl + btot));
        }
    }
    __syncthreads();

    int excl_t = s_excl + incl - deg;
    if (i < N_NODES) {
        g_row_ptr[i] = excl_t;
        g_cursor[i]  = excl_t;
        if (i == N_NODES - 1) g_row_ptr[N_NODES] = excl_t + deg;
        g_norm_src[i] = rsqrtf(fmaxf((float)g_deg_out[i], 1.0f));
    }
}

// ---------------- scatter edges into packed CSR --------------------------
__global__ void scatter_edges_kernel(const int* __restrict__ src,
                                     const int* __restrict__ dst) {
    int e = blockIdx.x * blockDim.x + threadIdx.x;
    if (e < N_EDGES) {
        int s = src[e];
        int d = dst[e];
        int pos = atomicAdd(&g_cursor[d], 1);
        float nd = rsqrtf(fmaxf((float)g_deg_in[d], 1.0f));
        g_csr[pos] = make_int2(s, __float_as_int(g_norm_src[s] * nd));
    }
}

// ---------------- SpMM (CSR gather, fp16 rows): one warp per dst node ----
// 8-edge groups: two independent 4-term HFMA2 chains -> more loads in flight.
__global__ __launch_bounds__(256)
void spmm_csr_kernel(int in_sel) {
    int node = blockIdx.x * (blockDim.x >> 5) + (threadIdx.x >> 5);
    if (node >= N_NODES) return;
    int lane = threadIdx.x & 31;

    const unsigned* __restrict__ h = (in_sel < 0) ? g_feat16 : g_h16[in_sel];
    const int2* __restrict__ csr = g_csr;

    int beg = g_row_ptr[node];
    int end = g_row_ptr[node + 1];

    float4 acc = make_float4(0.f, 0.f, 0.f, 0.f);

    int i = beg;
    for (; i + 7 < end; i += 8) {
        int2 e0 = csr[i];
        int2 e1 = csr[i + 1];
        int2 e2 = csr[i + 2];
        int2 e3 = csr[i + 3];
        int2 e4 = csr[i + 4];
        int2 e5 = csr[i + 5];
        int2 e6 = csr[i + 6];
        int2 e7 = csr[i + 7];
        uint2 v0 = ((const uint2*)(h + (size_t)e0.x * DIM2))[lane];
        uint2 v1 = ((const uint2*)(h + (size_t)e1.x * DIM2))[lane];
        uint2 v2 = ((const uint2*)(h + (size_t)e2.x * DIM2))[lane];
        uint2 v3 = ((const uint2*)(h + (size_t)e3.x * DIM2))[lane];
        uint2 v4 = ((const uint2*)(h + (size_t)e4.x * DIM2))[lane];
        uint2 v5 = ((const uint2*)(h + (size_t)e5.x * DIM2))[lane];
        uint2 v6 = ((const uint2*)(h + (size_t)e6.x * DIM2))[lane];
        uint2 v7 = ((const uint2*)(h + (size_t)e7.x * DIM2))[lane];

        __half2 w0 = __float2half2_rn(__int_as_float(e0.y));
        __half2 w1 = __float2half2_rn(__int_as_float(e1.y));
        __half2 w2 = __float2half2_rn(__int_as_float(e2.y));
        __half2 w3 = __float2half2_rn(__int_as_float(e3.y));
        __half2 w4 = __float2half2_rn(__int_as_float(e4.y));
        __half2 w5 = __float2half2_rn(__int_as_float(e5.y));
        __half2 w6 = __float2half2_rn(__int_as_float(e6.y));
        __half2 w7 = __float2half2_rn(__int_as_float(e7.y));

        // chain A: edges 0-3
        __half2 p0 = __hmul2(*(__half2*)&v0.x, w0);
        __half2 p1 = __hmul2(*(__half2*)&v0.y, w0);
        p0 = __hfma2(*(__half2*)&v1.x, w1, p0);
        p1 = __hfma2(*(__half2*)&v1.y, w1, p1);
        p0 = __hfma2(*(__half2*)&v2.x, w2, p0);
        p1 = __hfma2(*(__half2*)&v2.y, w2, p1);
        p0 = __hfma2(*(__half2*)&v3.x, w3, p0);
        p1 = __hfma2(*(__half2*)&v3.y, w3, p1);
        // chain B: edges 4-7
        __half2 q0 = __hmul2(*(__half2*)&v4.x, w4);
        __half2 q1 = __hmul2(*(__half2*)&v4.y, w4);
        q0 = __hfma2(*(__half2*)&v5.x, w5, q0);
        q1 = __hfma2(*(__half2*)&v5.y, w5, q1);
        q0 = __hfma2(*(__half2*)&v6.x, w6, q0);
        q1 = __hfma2(*(__half2*)&v6.y, w6, q1);
        q0 = __hfma2(*(__half2*)&v7.x, w7, q0);
        q1 = __hfma2(*(__half2*)&v7.y, w7, q1);

        float2 f0 = __half22float2(p0);
        float2 f1 = __half22float2(p1);
        float2 g0 = __half22float2(q0);
        float2 g1 = __half22float2(q1);
        acc.x += f0.x + g0.x; acc.y += f0.y + g0.y;
        acc.z += f1.x + g1.x; acc.w += f1.y + g1.y;
    }
    for (; i + 3 < end; i += 4) {
        int2 e0 = csr[i];
        int2 e1 = csr[i + 1];
        int2 e2 = csr[i + 2];
        int2 e3 = csr[i + 3];
        uint2 v0 = ((const uint2*)(h + (size_t)e0.x * DIM2))[lane];
        uint2 v1 = ((const uint2*)(h + (size_t)e1.x * DIM2))[lane];
        uint2 v2 = ((const uint2*)(h + (size_t)e2.x * DIM2))[lane];
        uint2 v3 = ((const uint2*)(h + (size_t)e3.x * DIM2))[lane];
        __half2 w0 = __float2half2_rn(__int_as_float(e0.y));
        __half2 w1 = __float2half2_rn(__int_as_float(e1.y));
        __half2 w2 = __float2half2_rn(__int_as_float(e2.y));
        __half2 w3 = __float2half2_rn(__int_as_float(e3.y));
        __half2 p0 = __hmul2(*(__half2*)&v0.x, w0);
        __half2 p1 = __hmul2(*(__half2*)&v0.y, w0);
        p0 = __hfma2(*(__half2*)&v1.x, w1, p0);
        p1 = __hfma2(*(__half2*)&v1.y, w1, p1);
        p0 = __hfma2(*(__half2*)&v2.x, w2, p0);
        p1 = __hfma2(*(__half2*)&v2.y, w2, p1);
        p0 = __hfma2(*(__half2*)&v3.x, w3, p0);
        p1 = __hfma2(*(__half2*)&v3.y, w3, p1);
        float2 f0 = __half22float2(p0);
        float2 f1 = __half22float2(p1);
        acc.x += f0.x; acc.y += f0.y; acc.z += f1.x; acc.w += f1.y;
    }
    for (; i < end; i++) {
        int2 e0 = csr[i];
        float w = __int_as_float(e0.y);
        uint2 v0 = ((const uint2*)(h + (size_t)e0.x * DIM2))[lane];
        float2 a = __half22float2(*(__half2*)&v0.x);
        float2 b = __half22float2(*(__half2*)&v0.y);
        acc.x += a.x * w; acc.y += a.y * w; acc.z += b.x * w; acc.w += b.y * w;
    }

    __half2 h01 = __floats2half2_rn(acc.x, acc.y);
    __half2 h23 = __floats2half2_rn(acc.z, acc.w);
    uint2 pk;
    pk.x = *(unsigned*)&h01;
    pk.y = *(unsigned*)&h23;
    ((uint2*)(g_agg16 + (size_t)node * DIM2))[lane] = pk;
}

// ---------------- fp16 tensor GEMM: out = relu(agg @ W + b) --------------
// 2-pass W-compensated fp16. Tile: BM=128, BN=128. 256 threads = 8 warps
// (4M x 2N), warp tile 32x64.
__global__ __launch_bounds__(256, 2)
void gemm_fp16_kernel(const float* __restrict__ bias_p,
                      float* __restrict__ ext_out,
                      int layer, int out_sel) {
    __shared__ uint32_t Apk[128 * 20];   // 128 rows x 16 u32 (32 k) + pad
    __shared__ uint32_t Whi[16 * 136];   // 16 k2 x 128 n + pad
    __shared__ uint32_t Wlo[16 * 136];

    const unsigned* __restrict__ Wh = g_Whl[0] + (size_t)layer * DIM2 * DIM;
    const unsigned* __restrict__ Wl = g_Whl[1] + (size_t)layer * DIM2 * DIM;

    const int tid  = threadIdx.x;
    const int lane = tid & 31;
    const int wrp  = tid >> 5;
    const int wm   = wrp & 3;       // 4 M quarters (32 rows each)
    const int wn   = wrp >> 2;      // 2 N halves (64 cols each)
    const int gid  = lane >> 2;
    const int tg   = lane & 3;
    const int rowBase = blockIdx.x * 128;

    float C[2][8][4];
    #pragma unroll
    for (int mt = 0; mt < 2; mt++)
        #pragma unroll
        for (int nt = 0; nt < 8; nt++)
            #pragma unroll
            for (int q = 0; q < 4; q++) C[mt][nt][q] = 0.0f;

    for (int kc2 = 0; kc2 < DIM2; kc2 += 16) {   // 4 chunks of 32 k
        if (kc2) __syncthreads();

        #pragma unroll
        for (int it = 0; it < 2; it++) {
            int f  = tid + it * 256;
            int r  = f >> 2;
            int cc = (f & 3) * 4;
            int grow = rowBase + r;
            uint4 v = make_uint4(0u, 0u, 0u, 0u);
            if (grow < N_NODES)
                v = *(const uint4*)&g_agg16[(size_t)grow * DIM2 + kc2 + cc];
            *(uint4*)&Apk[r * 20 + cc] = v;
        }
        #pragma unroll
        for (int it = 0; it < 2; it++) {
            int f  = tid + it * 256;
            int kk = f >> 5;
            int nn = (f & 31) * 4;
            *(uint4*)&Whi[kk * 136 + nn] =
                *(const uint4*)&Wh[(size_t)(kc2 + kk) * DIM + nn];
            *(uint4*)&Wlo[kk * 136 + nn] =
                *(const uint4*)&Wl[(size_t)(kc2 + kk) * DIM + nn];
        }
        __syncthreads();

        #pragma unroll
        for (int k8 = 0; k8 < 2; k8++) {
            uint32_t a[2][4];
            #pragma unroll
            for (int mt = 0; mt < 2; mt++) {
                int r0 = wm * 32 + mt * 16 + gid;
                int c0 = k8 * 8 + tg;
                a[mt][0] = Apk[r0 * 20 + c0];
                a[mt][1] = Apk[(r0 + 8) * 20 + c0];
                a[mt][2] = Apk[r0 * 20 + c0 + 4];
                a[mt][3] = Apk[(r0 + 8) * 20 + c0 + 4];
            }
            #pragma unroll
            for (int nt = 0; nt < 8; nt++) {
                int n = wn * 64 + nt * 8 + gid;
                int k = k8 * 8 + tg;
                uint32_t bh0 = Whi[k * 136 + n];
                uint32_t bh1 = Whi[(k + 4) * 136 + n];
                uint32_t bl0 = Wlo[k * 136 + n];
                uint32_t bl1 = Wlo[(k + 4) * 136 + n];
                #pragma unroll
                for (int mt = 0; mt < 2; mt++) {
                    mma_f16(C[mt][nt], a[mt], bh0, bh1);   // A * Whi
                    mma_f16(C[mt][nt], a[mt], bl0, bl1);   // A * Wlo
                }
            }
        }
    }

    unsigned* __restrict__ out16 = (out_sel < 0) ? nullptr : g_h16[out_sel];
    #pragma unroll
    for (int nt = 0; nt < 8; nt++) {
        int col = wn * 64 + nt * 8 + 2 * tg;
        float b0 = bias_p[col];
        float b1 = bias_p[col + 1];
        #pragma unroll
        for (int mt = 0; mt < 2; mt++) {
            int row = rowBase + wm * 32 + mt * 16 + gid;
            float x0 = fmaxf(C[mt][nt][0] + b0, 0.f);
            float y0 = fmaxf(C[mt][nt][1] + b1, 0.f);
            float x1 = fmaxf(C[mt][nt][2] + b0, 0.f);
            float y1 = fmaxf(C[mt][nt][3] + b1, 0.f);
            if (out_sel < 0) {
                if (row < N_NODES)
                    *(float2*)&ext_out[(size_t)row * DIM + col] =
                        make_float2(x0, y0);
                if (row + 8 < N_NODES)
                    *(float2*)&ext_out[(size_t)(row + 8) * DIM + col] =
                        make_float2(x1, y1);
            } else {
                if (row < N_NODES) {
                    __half2 hv = __floats2half2_rn(x0, y0);
                    out16[(size_t)row * DIM2 + (col >> 1)] = *(unsigned*)&hv;
                }
                if (row + 8 < N_NODES) {
                    __half2 hv = __floats2half2_rn(x1, y1);
                    out16[(size_t)(row + 8) * DIM2 + (col >> 1)] = *(unsigned*)&hv;
                }
            }
        }
    }
}

// ---------------- launch ----------------
extern "C" void kernel_launch(void* const* d_in, const int* in_sizes, int n_in,
                              void* d_out, int out_size) {
    const float* feat = (const float*)d_in[0];   // [N, D]
    const int*   src  = (const int*)d_in[1];     // [E]
    const int*   dst  = (const int*)d_in[2];     // [E]
    const float* W    = (const float*)d_in[3];   // [L, D, D]
    const float* b    = (const float*)d_in[4];   // [L, D]
    float* out = (float*)d_out;                  // [N, D]

    (void)in_sizes; (void)n_in; (void)out_size;

    // ---- prologue: 3 kernels (deg/scan_state are zero on entry) ----
    init_kernel<<<FEAT_BLOCKS + WSPL_BLOCKS + CNT_BLOCKS, 256>>>(
        feat, W, src, dst);
    scan_fused_kernel<<<SCAN_BLOCKS, 256>>>();
    scatter_edges_kernel<<<(N_EDGES + 255) / 256, 256>>>(src, dst);

    const int warps_per_block = 256 / 32;
    const int spmm_blocks = (N_NODES + warps_per_block - 1) / warps_per_block;
    const int gemm_blocks = (N_NODES + 127) / 128;   // 391

    for (int l = 0; l < LAYERS; l++) {
        int in_sel  = (l == 0) ? -1 : ((l - 1) & 1);
        int out_sel = (l == LAYERS - 1) ? -1 : (l & 1);

        spmm_csr_kernel<<<spmm_blocks, 256>>>(in_sel);
        gemm_fp16_kernel<<<gemm_blocks, 256>>>(
            b + (size_t)l * DIM, out, l, out_sel);
    }

    // restore zeroed state for the next (identical) launch
    cleanup_kernel<<<SCAN_BLOCKS, 256>>>();
}

// round 16
// speedup vs baseline: 1.1092x; 1.0059x over previous
#include <cuda_runtime.h>
#include <cuda_fp16.h>
#include <cstdint>

#define N_NODES 50000
#define N_EDGES 800000
#define DIM     128
#define DIM2    64                    // DIM/2 (u32 units per row)
#define DIM4    32                    // DIM/4 (uint4... actually u32/4 = 16)
#define LAYERS  5

#define SCAN_BLOCKS 196               // ceil(50000/256)
#define FEAT_BLOCKS 12500             // 50000*64/256
#define WSPL_BLOCKS 160               // 5*64*128/256
#define CNT_BLOCKS  3125              // 800000/256

#define FLAG_AGG    (1u << 30)
#define FLAG_PRE    (2u << 30)
#define VAL_MASK    0x3FFFFFFFu

// ---------------- scratch (no allocation allowed) ----------------
// g_deg_*, g_scan_state are zero at module load and restored to zero by
// cleanup_kernel at the end of every launch (launch-invariant state).
__device__ unsigned g_feat16[N_NODES * DIM2];    // feat as half2
__device__ unsigned g_h16[2][N_NODES * DIM2];    // ping-pong hidden, half2
__device__ unsigned g_agg16[N_NODES * DIM2];     // aggregation, half2
__device__ unsigned g_Whl[2][LAYERS * DIM2 * DIM]; // W hi/lo, [l][k2][n]
__device__ int      g_deg_out[N_NODES];
__device__ int      g_deg_in[N_NODES];
__device__ float    g_norm_src[N_NODES];
__device__ int      g_row_ptr[N_NODES + 1];
__device__ int      g_cursor[N_NODES];
__device__ int2     g_csr[N_EDGES];
__device__ unsigned g_scan_state[SCAN_BLOCKS];

// fp16 mma: D(16x8,f32) += A(16x16,f16) * B(16x8,f16)
__device__ __forceinline__ void mma_f16(float c[4], const uint32_t a[4],
                                        uint32_t b0, uint32_t b1) {
    asm volatile(
        "mma.sync.aligned.m16n8k16.row.col.f32.f16.f16.f32 "
        "{%0,%1,%2,%3}, {%4,%5,%6,%7}, {%8,%9}, {%0,%1,%2,%3};"
        : "+f"(c[0]), "+f"(c[1]), "+f"(c[2]), "+f"(c[3])
        : "r"(a[0]), "r"(a[1]), "r"(a[2]), "r"(a[3]), "r"(b0), "r"(b1));
}

// ---------------- fused init: feat->fp16, W split, degree count ------------
__global__ __launch_bounds__(256)
void init_kernel(const float* __restrict__ feat, const float* __restrict__ W,
                 const int* __restrict__ src, const int* __restrict__ dst) {
    int bid = blockIdx.x;
    if (bid < FEAT_BLOCKS) {
        int i = bid * 256 + threadIdx.x;
        float2 f = ((const float2*)feat)[i];
        __half2 h = __floats2half2_rn(f.x, f.y);
        g_feat16[i] = *(unsigned*)&h;
    } else if (bid < FEAT_BLOCKS + WSPL_BLOCKS) {
        int i = (bid - FEAT_BLOCKS) * 256 + threadIdx.x;
        int n  = i & 127;
        int k2 = (i >> 7) & 63;
        int l  = i >> 13;
        float w0 = W[l * DIM * DIM + (2 * k2)     * DIM + n];
        float w1 = W[l * DIM * DIM + (2 * k2 + 1) * DIM + n];
        __half h0 = __float2half_rn(w0);
        __half h1 = __float2half_rn(w1);
        float r0 = w0 - __half2float(h0);
        float r1 = w1 - __half2float(h1);
        __half2 hi = __halves2half2(h0, h1);
        __half2 lo = __floats2half2_rn(r0, r1);
        g_Whl[0][i] = *(unsigned*)&hi;
        g_Whl[1][i] = *(unsigned*)&lo;
    } else {
        int e = (bid - FEAT_BLOCKS - WSPL_BLOCKS) * 256 + threadIdx.x;
        if (e < N_EDGES) {
            atomicAdd(&g_deg_out[src[e]], 1);
            atomicAdd(&g_deg_in[dst[e]], 1);
        }
    }
}

// ---------------- cleanup: restore zeroed state for next launch ------------
__global__ __launch_bounds__(256)
void cleanup_kernel() {
    int i = blockIdx.x * 256 + threadIdx.x;
    if (i < N_NODES) { g_deg_out[i] = 0; g_deg_in[i] = 0; }
    if (i < SCAN_BLOCKS) g_scan_state[i] = 0u;
}

// ---------------- single-kernel decoupled-lookback scan ----------------
__global__ __launch_bounds__(256)
void scan_fused_kernel() {
    __shared__ int wsum[8];
    __shared__ int s_excl;
    int tid  = threadIdx.x;
    int lane = tid & 31;
    int wid  = tid >> 5;
    int bid  = blockIdx.x;
    int i    = bid * 256 + tid;

    int deg = (i < N_NODES) ? g_deg_in[i] : 0;

    int v = deg;
    #pragma unroll
    for (int o = 1; o < 32; o <<= 1) {
        int n = __shfl_up_sync(0xFFFFFFFFu, v, o);
        if (lane >= o) v += n;
    }
    if (lane == 31) wsum[wid] = v;
    __syncthreads();
    if (wid == 0) {
        int s = (lane < 8) ? wsum[lane] : 0;
        #pragma unroll
        for (int o = 1; o < 8; o <<= 1) {
            int n = __shfl_up_sync(0xFFFFFFFFu, s, o);
            if (lane >= o) s += n;
        }
        if (lane < 8) wsum[lane] = s;
    }
    __syncthreads();
    int incl = v + (wid > 0 ? wsum[wid - 1] : 0);
    int btot = wsum[7];

    if (tid == 0) {
        unsigned pub = (bid == 0) ? (FLAG_PRE | (unsigned)btot)
                                  : (FLAG_AGG | (unsigned)btot);
        atomicExch(&g_scan_state[bid], pub);
        if (bid == 0) s_excl = 0;
    }

    if (bid > 0 && wid == 0) {
        int excl = 0;
        int look = bid - 1;
        while (true) {
            int idx = look - lane;
            unsigned s;
            do {
                s = (idx >= 0) ? atomicAdd(&g_scan_state[idx], 0u)
                               : FLAG_PRE;
            } while (s == 0u);
            unsigned pmask = __ballot_sync(0xFFFFFFFFu, (s >> 30) == 2u);
            int val;
            if (pmask) {
                int plane = __ffs(pmask) - 1;
                val = (lane <= plane) ? (int)(s & VAL_MASK) : 0;
            } else {
                val = (int)(s & VAL_MASK);
            }
            #pragma unroll
            for (int o = 16; o > 0; o >>= 1)
                val += __shfl_down_sync(0xFFFFFFFFu, val, o);
            excl += __shfl_sync(0xFFFFFFFFu, val, 0);
            if (pmask) break;
            look -= 32;
        }
        if (lane == 0) {
            s_excl = excl;
            atomicExch(&g_scan_state[bid], FLAG_PRE | (unsigned)(excl + btot));
        }
    }
    __syncthreads();

    int excl_t = s_excl + incl - deg;
    if (i < N_NODES) {
        g_row_ptr[i] = excl_t;
        g_cursor[i]  = excl_t;
        if (i == N_NODES - 1) g_row_ptr[N_NODES] = excl_t + deg;
        g_norm_src[i] = rsqrtf(fmaxf((float)g_deg_out[i], 1.0f));
    }
}

// ---------------- scatter edges into packed CSR --------------------------
__global__ void scatter_edges_kernel(const int* __restrict__ src,
                                     const int* __restrict__ dst) {
    int e = blockIdx.x * blockDim.x + threadIdx.x;
    if (e < N_EDGES) {
        int s = src[e];
        int d = dst[e];
        int pos = atomicAdd(&g_cursor[d], 1);
        float nd = rsqrtf(fmaxf((float)g_deg_in[d], 1.0f));
        g_csr[pos] = make_int2(s, __float_as_int(g_norm_src[s] * nd));
    }
}

// ---------------- SpMM (CSR gather, fp16 rows): HALF-warp per dst node ----
// Row = 256 B = 16 lanes x uint4. One warp serves two nodes; per edge-pair
// the warp issues 1 LDG.128 + 1 csr load + 1 cvt (vs 2 each before).
// 4-edge half2 chains (p0..p3), promoted to fp32 per group.
__global__ __launch_bounds__(256)
void spmm_csr_kernel(int in_sel) {
    int warp = blockIdx.x * (blockDim.x >> 5) + (threadIdx.x >> 5);
    int half = (threadIdx.x >> 4) & 1;
    int node = warp * 2 + half;
    if (node >= N_NODES) return;
    int lane16 = threadIdx.x & 15;

    const unsigned* __restrict__ h = (in_sel < 0) ? g_feat16 : g_h16[in_sel];
    const int2* __restrict__ csr = g_csr;

    int beg = g_row_ptr[node];
    int end = g_row_ptr[node + 1];

    float f0 = 0.f, f1 = 0.f, f2 = 0.f, f3 = 0.f;
    float f4 = 0.f, f5 = 0.f, f6 = 0.f, f7 = 0.f;

    int i = beg;
    for (; i + 3 < end; i += 4) {
        int2 e0 = csr[i];
        int2 e1 = csr[i + 1];
        int2 e2 = csr[i + 2];
        int2 e3 = csr[i + 3];
        uint4 v0 = ((const uint4*)(h + (size_t)e0.x * DIM2))[lane16];
        uint4 v1 = ((const uint4*)(h + (size_t)e1.x * DIM2))[lane16];
        uint4 v2 = ((const uint4*)(h + (size_t)e2.x * DIM2))[lane16];
        uint4 v3 = ((const uint4*)(h + (size_t)e3.x * DIM2))[lane16];
        __half2 w0 = __float2half2_rn(__int_as_float(e0.y));
        __half2 w1 = __float2half2_rn(__int_as_float(e1.y));
        __half2 w2 = __float2half2_rn(__int_as_float(e2.y));
        __half2 w3 = __float2half2_rn(__int_as_float(e3.y));

        // four independent 4-edge chains (one per half2 slot)
        __half2 p0 = __hmul2(*(__half2*)&v0.x, w0);
        __half2 p1 = __hmul2(*(__half2*)&v0.y, w0);
        __half2 p2 = __hmul2(*(__half2*)&v0.z, w0);
        __half2 p3 = __hmul2(*(__half2*)&v0.w, w0);
        p0 = __hfma2(*(__half2*)&v1.x, w1, p0);
        p1 = __hfma2(*(__half2*)&v1.y, w1, p1);
        p2 = __hfma2(*(__half2*)&v1.z, w1, p2);
        p3 = __hfma2(*(__half2*)&v1.w, w1, p3);
        p0 = __hfma2(*(__half2*)&v2.x, w2, p0);
        p1 = __hfma2(*(__half2*)&v2.y, w2, p1);
        p2 = __hfma2(*(__half2*)&v2.z, w2, p2);
        p3 = __hfma2(*(__half2*)&v2.w, w2, p3);
        p0 = __hfma2(*(__half2*)&v3.x, w3, p0);
        p1 = __hfma2(*(__half2*)&v3.y, w3, p1);
        p2 = __hfma2(*(__half2*)&v3.z, w3, p2);
        p3 = __hfma2(*(__half2*)&v3.w, w3, p3);

        float2 t;
        t = __half22float2(p0); f0 += t.x; f1 += t.y;
        t = __half22float2(p1); f2 += t.x; f3 += t.y;
        t = __half22float2(p2); f4 += t.x; f5 += t.y;
        t = __half22float2(p3); f6 += t.x; f7 += t.y;
    }
    for (; i < end; i++) {
        int2 e0 = csr[i];
        float w = __int_as_float(e0.y);
        uint4 v0 = ((const uint4*)(h + (size_t)e0.x * DIM2))[lane16];
        float2 a;
        a = __half22float2(*(__half2*)&v0.x); f0 += a.x * w; f1 += a.y * w;
        a = __half22float2(*(__half2*)&v0.y); f2 += a.x * w; f3 += a.y * w;
        a = __half22float2(*(__half2*)&v0.z); f4 += a.x * w; f5 += a.y * w;
        a = __half22float2(*(__half2*)&v0.w); f6 += a.x * w; f7 += a.y * w;
    }

    __half2 o0 = __floats2half2_rn(f0, f1);
    __half2 o1 = __floats2half2_rn(f2, f3);
    __half2 o2 = __floats2half2_rn(f4, f5);
    __half2 o3 = __floats2half2_rn(f6, f7);
    uint4 pk;
    pk.x = *(unsigned*)&o0;
    pk.y = *(unsigned*)&o1;
    pk.z = *(unsigned*)&o2;
    pk.w = *(unsigned*)&o3;
    ((uint4*)(g_agg16 + (size_t)node * DIM2))[lane16] = pk;
}

// ---------------- fp16 tensor GEMM: out = relu(agg @ W + b) --------------
// 2-pass W-compensated fp16. Tile: BM=128, BN=128. 256 threads = 8 warps
// (4M x 2N), warp tile 32x64.
__global__ __launch_bounds__(256, 2)
void gemm_fp16_kernel(const float* __restrict__ bias_p,
                      float* __restrict__ ext_out,
                      int layer, int out_sel) {
    __shared__ uint32_t Apk[128 * 20];   // 128 rows x 16 u32 (32 k) + pad
    __shared__ uint32_t Whi[16 * 136];   // 16 k2 x 128 n + pad
    __shared__ uint32_t Wlo[16 * 136];

    const unsigned* __restrict__ Wh = g_Whl[0] + (size_t)layer * DIM2 * DIM;
    const unsigned* __restrict__ Wl = g_Whl[1] + (size_t)layer * DIM2 * DIM;

    const int tid  = threadIdx.x;
    const int lane = tid & 31;
    const int wrp  = tid >> 5;
    const int wm   = wrp & 3;       // 4 M quarters (32 rows each)
    const int wn   = wrp >> 2;      // 2 N halves (64 cols each)
    const int gid  = lane >> 2;
    const int tg   = lane & 3;
    const int rowBase = blockIdx.x * 128;

    float C[2][8][4];
    #pragma unroll
    for (int mt = 0; mt < 2; mt++)
        #pragma unroll
        for (int nt = 0; nt < 8; nt++)
            #pragma unroll
            for (int q = 0; q < 4; q++) C[mt][nt][q] = 0.0f;

    for (int kc2 = 0; kc2 < DIM2; kc2 += 16) {   // 4 chunks of 32 k
        if (kc2) __syncthreads();

        #pragma unroll
        for (int it = 0; it < 2; it++) {
            int f  = tid + it * 256;
            int r  = f >> 2;
            int cc = (f & 3) * 4;
            int grow = rowBase + r;
            uint4 v = make_uint4(0u, 0u, 0u, 0u);
            if (grow < N_NODES)
                v = *(const uint4*)&g_agg16[(size_t)grow * DIM2 + kc2 + cc];
            *(uint4*)&Apk[r * 20 + cc] = v;
        }
        #pragma unroll
        for (int it = 0; it < 2; it++) {
            int f  = tid + it * 256;
            int kk = f >> 5;
            int nn = (f & 31) * 4;
            *(uint4*)&Whi[kk * 136 + nn] =
                *(const uint4*)&Wh[(size_t)(kc2 + kk) * DIM + nn];
            *(uint4*)&Wlo[kk * 136 + nn] =
                *(const uint4*)&Wl[(size_t)(kc2 + kk) * DIM + nn];
        }
        __syncthreads();

        #pragma unroll
        for (int k8 = 0; k8 < 2; k8++) {
            uint32_t a[2][4];
            #pragma unroll
            for (int mt = 0; mt < 2; mt++) {
                int r0 = wm * 32 + mt * 16 + gid;
                int c0 = k8 * 8 + tg;
                a[mt][0] = Apk[r0 * 20 + c0];
                a[mt][1] = Apk[(r0 + 8) * 20 + c0];
                a[mt][2] = Apk[r0 * 20 + c0 + 4];
                a[mt][3] = Apk[(r0 + 8) * 20 + c0 + 4];
            }
            #pragma unroll
            for (int nt = 0; nt < 8; nt++) {
                int n = wn * 64 + nt * 8 + gid;
                int k = k8 * 8 + tg;
                uint32_t bh0 = Whi[k * 136 + n];
                uint32_t bh1 = Whi[(k + 4) * 136 + n];
                uint32_t bl0 = Wlo[k * 136 + n];
                uint32_t bl1 = Wlo[(k + 4) * 136 + n];
                #pragma unroll
                for (int mt = 0; mt < 2; mt++) {
                    mma_f16(C[mt][nt], a[mt], bh0, bh1);   // A * Whi
                    mma_f16(C[mt][nt], a[mt], bl0, bl1);   // A * Wlo
                }
            }
        }
    }

    unsigned* __restrict__ out16 = (out_sel < 0) ? nullptr : g_h16[out_sel];
    #pragma unroll
    for (int nt = 0; nt < 8; nt++) {
        int col = wn * 64 + nt * 8 + 2 * tg;
        float b0 = bias_p[col];
        float b1 = bias_p[col + 1];
        #pragma unroll
        for (int mt = 0; mt < 2; mt++) {
            int row = rowBase + wm * 32 + mt * 16 + gid;
            float x0 = fmaxf(C[mt][nt][0] + b0, 0.f);
            float y0 = fmaxf(C[mt][nt][1] + b1, 0.f);
            float x1 = fmaxf(C[mt][nt][2] + b0, 0.f);
            float y1 = fmaxf(C[mt][nt][3] + b1, 0.f);
            if (out_sel < 0) {
                if (row < N_NODES)
                    *(float2*)&ext_out[(size_t)row * DIM + col] =
                        make_float2(x0, y0);
                if (row + 8 < N_NODES)
                    *(float2*)&ext_out[(size_t)(row + 8) * DIM + col] =
                        make_float2(x1, y1);
            } else {
                if (row < N_NODES) {
                    __half2 hv = __floats2half2_rn(x0, y0);
                    out16[(size_t)row * DIM2 + (col >> 1)] = *(unsigned*)&hv;
                }
                if (row + 8 < N_NODES) {
                    __half2 hv = __floats2half2_rn(x1, y1);
                    out16[(size_t)(row + 8) * DIM2 + (col >> 1)] = *(unsigned*)&hv;
                }
            }
        }
    }
}

// ---------------- launch ----------------
extern "C" void kernel_launch(void* const* d_in, const int* in_sizes, int n_in,
                              void* d_out, int out_size) {
    const float* feat = (const float*)d_in[0];   // [N, D]
    const int*   src  = (const int*)d_in[1];     // [E]
    const int*   dst  = (const int*)d_in[2];     // [E]
    const float* W    = (const float*)d_in[3];   // [L, D, D]
    const float* b    = (const float*)d_in[4];   // [L, D]
    float* out = (float*)d_out;                  // [N, D]

    (void)in_sizes; (void)n_in; (void)out_size;

    // ---- prologue: 3 kernels (deg/scan_state are zero on entry) ----
    init_kernel<<<FEAT_BLOCKS + WSPL_BLOCKS + CNT_BLOCKS, 256>>>(
        feat, W, src, dst);
    scan_fused_kernel<<<SCAN_BLOCKS, 256>>>();
    scatter_edges_kernel<<<(N_EDGES + 255) / 256, 256>>>(src, dst);

    const int nodes_per_block = 2 * (256 / 32);     // 16
    const int spmm_blocks = (N_NODES + nodes_per_block - 1) / nodes_per_block;
    const int gemm_blocks = (N_NODES + 127) / 128;   // 391

    for (int l = 0; l < LAYERS; l++) {
        int in_sel  = (l == 0) ? -1 : ((l - 1) & 1);
        int out_sel = (l == LAYERS - 1) ? -1 : (l & 1);

        spmm_csr_kernel<<<spmm_blocks, 256>>>(in_sel);
        gemm_fp16_kernel<<<gemm_blocks, 256>>>(
            b + (size_t)l * DIM, out, l, out_sel);
    }

    // restore zeroed state for the next (identical) launch
    cleanup_kernel<<<SCAN_BLOCKS, 256>>>();
}

// round 17
// speedup vs baseline: 1.1191x; 1.0089x over previous
#include <cuda_runtime.h>
#include <cuda_fp16.h>
#include <cstdint>

#define N_NODES 50000
#define N_EDGES 800000
#define DIM     128
#define DIM2    64                    // DIM/2 (u32 units per row)
#define LAYERS  5

#define SCAN_BLOCKS 196               // ceil(50000/256)
#define FEAT_BLOCKS 12500             // 50000*64/256
#define WSPL_BLOCKS 160               // 5*64*128/256
#define CNT_BLOCKS  782               // ceil(800000/1024), 4 edges/thread

#define FLAG_AGG    (1u << 30)
#define FLAG_PRE    (2u << 30)
#define VAL_MASK    0x3FFFFFFFu

// ---------------- scratch (no allocation allowed) ----------------
// g_deg_*, g_scan_state are zero at module load and restored to zero by
// cleanup_kernel at the end of every launch (launch-invariant state).
__device__ unsigned g_feat16[N_NODES * DIM2];    // feat as half2
__device__ unsigned g_h16[2][N_NODES * DIM2];    // ping-pong hidden, half2
__device__ unsigned g_agg16[N_NODES * DIM2];     // aggregation, half2
__device__ unsigned g_Whl[2][LAYERS * DIM2 * DIM]; // W hi/lo, [l][k2][n]
__device__ int      g_deg_out[N_NODES];
__device__ int      g_deg_in[N_NODES];
__device__ float    g_norm_src[N_NODES];
__device__ int      g_row_ptr[N_NODES + 1];
__device__ int      g_cursor[N_NODES];
__device__ int2     g_csr[N_EDGES];              // .x src, .y half2 weight
__device__ unsigned g_scan_state[SCAN_BLOCKS];

// fp16 mma: D(16x8,f32) += A(16x16,f16) * B(16x8,f16)
__device__ __forceinline__ void mma_f16(float c[4], const uint32_t a[4],
                                        uint32_t b0, uint32_t b1) {
    asm volatile(
        "mma.sync.aligned.m16n8k16.row.col.f32.f16.f16.f32 "
        "{%0,%1,%2,%3}, {%4,%5,%6,%7}, {%8,%9}, {%0,%1,%2,%3};"
        : "+f"(c[0]), "+f"(c[1]), "+f"(c[2]), "+f"(c[3])
        : "r"(a[0]), "r"(a[1]), "r"(a[2]), "r"(a[3]), "r"(b0), "r"(b1));
}

// ---------------- fused init: feat->fp16, W split, degree count ------------
__global__ __launch_bounds__(256)
void init_kernel(const float* __restrict__ feat, const float* __restrict__ W,
                 const int* __restrict__ src, const int* __restrict__ dst) {
    int bid = blockIdx.x;
    if (bid < FEAT_BLOCKS) {
        int i = bid * 256 + threadIdx.x;
        float2 f = ((const float2*)feat)[i];
        __half2 h = __floats2half2_rn(f.x, f.y);
        g_feat16[i] = *(unsigned*)&h;
    } else if (bid < FEAT_BLOCKS + WSPL_BLOCKS) {
        int i = (bid - FEAT_BLOCKS) * 256 + threadIdx.x;
        int n  = i & 127;
        int k2 = (i >> 7) & 63;
        int l  = i >> 13;
        float w0 = W[l * DIM * DIM + (2 * k2)     * DIM + n];
        float w1 = W[l * DIM * DIM + (2 * k2 + 1) * DIM + n];
        __half h0 = __float2half_rn(w0);
        __half h1 = __float2half_rn(w1);
        float r0 = w0 - __half2float(h0);
        float r1 = w1 - __half2float(h1);
        __half2 hi = __halves2half2(h0, h1);
        __half2 lo = __floats2half2_rn(r0, r1);
        g_Whl[0][i] = *(unsigned*)&hi;
        g_Whl[1][i] = *(unsigned*)&lo;
    } else {
        // 4 independent edges per thread (strided within a 1024-edge chunk)
        int base = (bid - FEAT_BLOCKS - WSPL_BLOCKS) * 1024 + threadIdx.x;
        #pragma unroll
        for (int r = 0; r < 4; r++) {
            int e = base + r * 256;
            if (e < N_EDGES) {
                atomicAdd(&g_deg_out[src[e]], 1);
                atomicAdd(&g_deg_in[dst[e]], 1);
            }
        }
    }
}

// ---------------- cleanup: restore zeroed state for next launch ------------
__global__ __launch_bounds__(256)
void cleanup_kernel() {
    int i = blockIdx.x * 256 + threadIdx.x;
    if (i < N_NODES) { g_deg_out[i] = 0; g_deg_in[i] = 0; }
    if (i < SCAN_BLOCKS) g_scan_state[i] = 0u;
}

// ---------------- single-kernel decoupled-lookback scan ----------------
__global__ __launch_bounds__(256)
void scan_fused_kernel() {
    __shared__ int wsum[8];
    __shared__ int s_excl;
    int tid  = threadIdx.x;
    int lane = tid & 31;
    int wid  = tid >> 5;
    int bid  = blockIdx.x;
    int i    = bid * 256 + tid;

    int deg = (i < N_NODES) ? g_deg_in[i] : 0;

    int v = deg;
    #pragma unroll
    for (int o = 1; o < 32; o <<= 1) {
        int n = __shfl_up_sync(0xFFFFFFFFu, v, o);
        if (lane >= o) v += n;
    }
    if (lane == 31) wsum[wid] = v;
    __syncthreads();
    if (wid == 0) {
        int s = (lane < 8) ? wsum[lane] : 0;
        #pragma unroll
        for (int o = 1; o < 8; o <<= 1) {
            int n = __shfl_up_sync(0xFFFFFFFFu, s, o);
            if (lane >= o) s += n;
        }
        if (lane < 8) wsum[lane] = s;
    }
    __syncthreads();
    int incl = v + (wid > 0 ? wsum[wid - 1] : 0);
    int btot = wsum[7];

    if (tid == 0) {
        unsigned pub = (bid == 0) ? (FLAG_PRE | (unsigned)btot)
                                  : (FLAG_AGG | (unsigned)btot);
        atomicExch(&g_scan_state[bid], pub);
        if (bid == 0) s_excl = 0;
    }

    if (bid > 0 && wid == 0) {
        int excl = 0;
        int look = bid - 1;
        while (true) {
            int idx = look - lane;
            unsigned s;
            do {
                s = (idx >= 0) ? atomicAdd(&g_scan_state[idx], 0u)
                               : FLAG_PRE;
            } while (s == 0u);
            unsigned pmask = __ballot_sync(0xFFFFFFFFu, (s >> 30) == 2u);
            int val;
            if (pmask) {
                int plane = __ffs(pmask) - 1;
                val = (lane <= plane) ? (int)(s & VAL_MASK) : 0;
            } else {
                val = (int)(s & VAL_MASK);
            }
            #pragma unroll
            for (int o = 16; o > 0; o >>= 1)
                val += __shfl_down_sync(0xFFFFFFFFu, val, o);
            excl += __shfl_sync(0xFFFFFFFFu, val, 0);
            if (pmask) break;
            look -= 32;
        }
        if (lane == 0) {
            s_excl = excl;
            atomicExch(&g_scan_state[bid], FLAG_PRE | (unsigned)(excl + btot));
        }
    }
    __syncthreads();

    int excl_t = s_excl + incl - deg;
    if (i < N_NODES) {
        g_row_ptr[i] = excl_t;
        g_cursor[i]  = excl_t;
        if (i == N_NODES - 1) g_row_ptr[N_NODES] = excl_t + deg;
        g_norm_src[i] = rsqrtf(fmaxf((float)g_deg_out[i], 1.0f));
    }
}

// ---------------- scatter edges: 4 independent chains per thread ----------
// Weight pre-packed as half2 (numerically identical to SpMM's former cvt).
__global__ __launch_bounds__(256)
void scatter_edges_kernel(const int* __restrict__ src,
                          const int* __restrict__ dst) {
    int base = blockIdx.x * 1024 + threadIdx.x;
    #pragma unroll
    for (int r = 0; r < 4; r++) {
        int e = base + r * 256;
        if (e < N_EDGES) {
            int s = src[e];
            int d = dst[e];
            int pos = atomicAdd(&g_cursor[d], 1);
            float nd = rsqrtf(fmaxf((float)g_deg_in[d], 1.0f));
            __half2 wp = __float2half2_rn(g_norm_src[s] * nd);
            g_csr[pos] = make_int2(s, (int)*(unsigned*)&wp);
        }
    }
}

// ---------------- SpMM (CSR gather, fp16 rows): half-warp per dst node ----
// csr indices double-buffered: group g+1's indices load while group g's
// rows gather -> removes one L2 latency per group from the critical path.
__global__ __launch_bounds__(256)
void spmm_csr_kernel(int in_sel) {
    int warp = blockIdx.x * (blockDim.x >> 5) + (threadIdx.x >> 5);
    int half = (threadIdx.x >> 4) & 1;
    int node = warp * 2 + half;
    if (node >= N_NODES) return;
    int lane16 = threadIdx.x & 15;

    const unsigned* __restrict__ h = (in_sel < 0) ? g_feat16 : g_h16[in_sel];
    const int2* __restrict__ csr = g_csr;

    int beg = g_row_ptr[node];
    int end = g_row_ptr[node + 1];
    int nfull = (end - beg) >> 2;

    float f0 = 0.f, f1 = 0.f, f2 = 0.f, f3 = 0.f;
    float f4 = 0.f, f5 = 0.f, f6 = 0.f, f7 = 0.f;

    int i = beg;
    int2 e0, e1, e2, e3;
    if (nfull > 0) {
        e0 = csr[i]; e1 = csr[i + 1]; e2 = csr[i + 2]; e3 = csr[i + 3];
    }
    for (int g = 0; g < nfull; g++) {
        int j = i + 4;
        int2 n0, n1, n2, n3;
        bool more = (g + 1 < nfull);
        if (more) {
            n0 = csr[j]; n1 = csr[j + 1]; n2 = csr[j + 2]; n3 = csr[j + 3];
        }
        uint4 v0 = ((const uint4*)(h + (size_t)e0.x * DIM2))[lane16];
        uint4 v1 = ((const uint4*)(h + (size_t)e1.x * DIM2))[lane16];
        uint4 v2 = ((const uint4*)(h + (size_t)e2.x * DIM2))[lane16];
        uint4 v3 = ((const uint4*)(h + (size_t)e3.x * DIM2))[lane16];
        __half2 w0 = *(__half2*)&e0.y;
        __half2 w1 = *(__half2*)&e1.y;
        __half2 w2 = *(__half2*)&e2.y;
        __half2 w3 = *(__half2*)&e3.y;

        __half2 p0 = __hmul2(*(__half2*)&v0.x, w0);
        __half2 p1 = __hmul2(*(__half2*)&v0.y, w0);
        __half2 p2 = __hmul2(*(__half2*)&v0.z, w0);
        __half2 p3 = __hmul2(*(__half2*)&v0.w, w0);
        p0 = __hfma2(*(__half2*)&v1.x, w1, p0);
        p1 = __hfma2(*(__half2*)&v1.y, w1, p1);
        p2 = __hfma2(*(__half2*)&v1.z, w1, p2);
        p3 = __hfma2(*(__half2*)&v1.w, w1, p3);
        p0 = __hfma2(*(__half2*)&v2.x, w2, p0);
        p1 = __hfma2(*(__half2*)&v2.y, w2, p1);
        p2 = __hfma2(*(__half2*)&v2.z, w2, p2);
        p3 = __hfma2(*(__half2*)&v2.w, w2, p3);
        p0 = __hfma2(*(__half2*)&v3.x, w3, p0);
        p1 = __hfma2(*(__half2*)&v3.y, w3, p1);
        p2 = __hfma2(*(__half2*)&v3.z, w3, p2);
        p3 = __hfma2(*(__half2*)&v3.w, w3, p3);

        float2 t;
        t = __half22float2(p0); f0 += t.x; f1 += t.y;
        t = __half22float2(p1); f2 += t.x; f3 += t.y;
        t = __half22float2(p2); f4 += t.x; f5 += t.y;
        t = __half22float2(p3); f6 += t.x; f7 += t.y;

        if (more) { e0 = n0; e1 = n1; e2 = n2; e3 = n3; }
        i = j;
    }
    // tail (<= 3 edges)
    for (; i < end; i++) {
        int2 e = csr[i];
        __half2 w = *(__half2*)&e.y;
        uint4 v0 = ((const uint4*)(h + (size_t)e.x * DIM2))[lane16];
        float2 a;
        float wf = __half2float(__low2half(w));
        a = __half22float2(*(__half2*)&v0.x); f0 += a.x * wf; f1 += a.y * wf;
        a = __half22float2(*(__half2*)&v0.y); f2 += a.x * wf; f3 += a.y * wf;
        a = __half22float2(*(__half2*)&v0.z); f4 += a.x * wf; f5 += a.y * wf;
        a = __half22float2(*(__half2*)&v0.w); f6 += a.x * wf; f7 += a.y * wf;
    }

    __half2 o0 = __floats2half2_rn(f0, f1);
    __half2 o1 = __floats2half2_rn(f2, f3);
    __half2 o2 = __floats2half2_rn(f4, f5);
    __half2 o3 = __floats2half2_rn(f6, f7);
    uint4 pk;
    pk.x = *(unsigned*)&o0;
    pk.y = *(unsigned*)&o1;
    pk.z = *(unsigned*)&o2;
    pk.w = *(unsigned*)&o3;
    ((uint4*)(g_agg16 + (size_t)node * DIM2))[lane16] = pk;
}

// ---------------- fp16 tensor GEMM: out = relu(agg @ W + b) --------------
// 2-pass W-compensated fp16. Tile: BM=128, BN=128. 256 threads = 8 warps
// (4M x 2N), warp tile 32x64.
__global__ __launch_bounds__(256, 2)
void gemm_fp16_kernel(const float* __restrict__ bias_p,
                      float* __restrict__ ext_out,
                      int layer, int out_sel) {
    __shared__ uint32_t Apk[128 * 20];   // 128 rows x 16 u32 (32 k) + pad
    __shared__ uint32_t Whi[16 * 136];   // 16 k2 x 128 n + pad
    __shared__ uint32_t Wlo[16 * 136];

    const unsigned* __restrict__ Wh = g_Whl[0] + (size_t)layer * DIM2 * DIM;
    const unsigned* __restrict__ Wl = g_Whl[1] + (size_t)layer * DIM2 * DIM;

    const int tid  = threadIdx.x;
    const int lane = tid & 31;
    const int wrp  = tid >> 5;
    const int wm   = wrp & 3;       // 4 M quarters (32 rows each)
    const int wn   = wrp >> 2;      // 2 N halves (64 cols each)
    const int gid  = lane >> 2;
    const int tg   = lane & 3;
    const int rowBase = blockIdx.x * 128;

    float C[2][8][4];
    #pragma unroll
    for (int mt = 0; mt < 2; mt++)
        #pragma unroll
        for (int nt = 0; nt < 8; nt++)
            #pragma unroll
            for (int q = 0; q < 4; q++) C[mt][nt][q] = 0.0f;

    for (int kc2 = 0; kc2 < DIM2; kc2 += 16) {   // 4 chunks of 32 k
        if (kc2) __syncthreads();

        #pragma unroll
        for (int it = 0; it < 2; it++) {
            int f  = tid + it * 256;
            int r  = f >> 2;
            int cc = (f & 3) * 4;
            int grow = rowBase + r;
            uint4 v = make_uint4(0u, 0u, 0u, 0u);
            if (grow < N_NODES)
                v = *(const uint4*)&g_agg16[(size_t)grow * DIM2 + kc2 + cc];
            *(uint4*)&Apk[r * 20 + cc] = v;
        }
        #pragma unroll
        for (int it = 0; it < 2; it++) {
            int f  = tid + it * 256;
            int kk = f >> 5;
            int nn = (f & 31) * 4;
            *(uint4*)&Whi[kk * 136 + nn] =
                *(const uint4*)&Wh[(size_t)(kc2 + kk) * DIM + nn];
            *(uint4*)&Wlo[kk * 136 + nn] =
                *(const uint4*)&Wl[(size_t)(kc2 + kk) * DIM + nn];
        }
        __syncthreads();

        #pragma unroll
        for (int k8 = 0; k8 < 2; k8++) {
            uint32_t a[2][4];
            #pragma unroll
            for (int mt = 0; mt < 2; mt++) {
                int r0 = wm * 32 + mt * 16 + gid;
                int c0 = k8 * 8 + tg;
                a[mt][0] = Apk[r0 * 20 + c0];
                a[mt][1] = Apk[(r0 + 8) * 20 + c0];
                a[mt][2] = Apk[r0 * 20 + c0 + 4];
                a[mt][3] = Apk[(r0 + 8) * 20 + c0 + 4];
            }
            #pragma unroll
            for (int nt = 0; nt < 8; nt++) {
                int n = wn * 64 + nt * 8 + gid;
                int k = k8 * 8 + tg;
                uint32_t bh0 = Whi[k * 136 + n];
                uint32_t bh1 = Whi[(k + 4) * 136 + n];
                uint32_t bl0 = Wlo[k * 136 + n];
                uint32_t bl1 = Wlo[(k + 4) * 136 + n];
                #pragma unroll
                for (int mt = 0; mt < 2; mt++) {
                    mma_f16(C[mt][nt], a[mt], bh0, bh1);   // A * Whi
                    mma_f16(C[mt][nt], a[mt], bl0, bl1);   // A * Wlo
                }
            }
        }
    }

    unsigned* __restrict__ out16 = (out_sel < 0) ? nullptr : g_h16[out_sel];
    #pragma unroll
    for (int nt = 0; nt < 8; nt++) {
        int col = wn * 64 + nt * 8 + 2 * tg;
        float b0 = bias_p[col];
        float b1 = bias_p[col + 1];
        #pragma unroll
        for (int mt = 0; mt < 2; mt++) {
            int row = rowBase + wm * 32 + mt * 16 + gid;
            float x0 = fmaxf(C[mt][nt][0] + b0, 0.f);
            float y0 = fmaxf(C[mt][nt][1] + b1, 0.f);
            float x1 = fmaxf(C[mt][nt][2] + b0, 0.f);
            float y1 = fmaxf(C[mt][nt][3] + b1, 0.f);
            if (out_sel < 0) {
                if (row < N_NODES)
                    *(float2*)&ext_out[(size_t)row * DIM + col] =
                        make_float2(x0, y0);
                if (row + 8 < N_NODES)
                    *(float2*)&ext_out[(size_t)(row + 8) * DIM + col] =
                        make_float2(x1, y1);
            } else {
                if (row < N_NODES) {
                    __half2 hv = __floats2half2_rn(x0, y0);
                    out16[(size_t)row * DIM2 + (col >> 1)] = *(unsigned*)&hv;
                }
                if (row + 8 < N_NODES) {
                    __half2 hv = __floats2half2_rn(x1, y1);
                    out16[(size_t)(row + 8) * DIM2 + (col >> 1)] = *(unsigned*)&hv;
                }
            }
        }
    }
}

// ---------------- launch ----------------
extern "C" void kernel_launch(void* const* d_in, const int* in_sizes, int n_in,
                              void* d_out, int out_size) {
    const float* feat = (const float*)d_in[0];   // [N, D]
    const int*   src  = (const int*)d_in[1];     // [E]
    const int*   dst  = (const int*)d_in[2];     // [E]
    const float* W    = (const float*)d_in[3];   // [L, D, D]
    const float* b    = (const float*)d_in[4];   // [L, D]
    float* out = (float*)d_out;                  // [N, D]

    (void)in_sizes; (void)n_in; (void)out_size;

    // ---- prologue: 3 kernels (deg/scan_state are zero on entry) ----
    init_kernel<<<FEAT_BLOCKS + WSPL_BLOCKS + CNT_BLOCKS, 256>>>(
        feat, W, src, dst);
    scan_fused_kernel<<<SCAN_BLOCKS, 256>>>();
    scatter_edges_kernel<<<CNT_BLOCKS, 256>>>(src, dst);

    const int nodes_per_block = 2 * (256 / 32);     // 16
    const int spmm_blocks = (N_NODES + nodes_per_block - 1) / nodes_per_block;
    const int gemm_blocks = (N_NODES + 127) / 128;   // 391

    for (int l = 0; l < LAYERS; l++) {
        int in_sel  = (l == 0) ? -1 : ((l - 1) & 1);
        int out_sel = (l == LAYERS - 1) ? -1 : (l & 1);

        spmm_csr_kernel<<<spmm_blocks, 256>>>(in_sel);
        gemm_fp16_kernel<<<gemm_blocks, 256>>>(
            b + (size_t)l * DIM, out, l, out_sel);
    }

    // restore zeroed state for the next (identical) launch
    cleanup_kernel<<<SCAN_BLOCKS, 256>>>();
}